// round 1
// baseline (speedup 1.0000x reference)
#include <cuda_runtime.h>
#include <math.h>

// Problem constants (fixed by the reference)
#define MAX_IN 64
#define D_MODEL 64
#define ROWS_PER_BLOCK 16
#define THREADS 256   // 16 groups of 16 threads; each group handles one row

__device__ __forceinline__ float gelu_tanh(float v) {
    // jax.nn.gelu approximate=True: 0.5*v*(1+tanh(sqrt(2/pi)*(v+0.044715 v^3)))
    const float c = 0.7978845608028654f;
    float u = c * (v + 0.044715f * v * v * v);
    return 0.5f * v * (1.0f + tanhf(u));
}

__global__ __launch_bounds__(THREADS)
void fe_kernel(const float* __restrict__ seg,
               const float* __restrict__ W,
               const float* __restrict__ b,
               const int*   __restrict__ lengths,
               float* __restrict__ out,
               int n)
{
    __shared__ float sx[ROWS_PER_BLOCK][MAX_IN];
    __shared__ int   slen[ROWS_PER_BLOCK];

    const int row0 = blockIdx.x * ROWS_PER_BLOCK;
    const int tid  = threadIdx.x;

    if (tid < ROWS_PER_BLOCK) {
        int r = row0 + tid;
        slen[tid] = (r < n) ? lengths[r] : 0;
    }
    __syncthreads();

    // Cooperative masked load of x rows into smem: 16 rows * 16 float4 = 256 float4
    {
        int r  = tid >> 4;        // row within block
        int c4 = tid & 15;        // float4 column
        int row = row0 + r;
        float4 v = make_float4(0.f, 0.f, 0.f, 0.f);
        if (row < n) {
            v = reinterpret_cast<const float4*>(seg)[(size_t)row * 16 + c4];
            int len = slen[r];
            int c = c4 * 4;
            if (c + 0 >= len) v.x = 0.f;
            if (c + 1 >= len) v.y = 0.f;
            if (c + 2 >= len) v.z = 0.f;
            if (c + 3 >= len) v.w = 0.f;
        }
        *reinterpret_cast<float4*>(&sx[r][c4 * 4]) = v;
    }
    __syncthreads();

    const int g = tid >> 4;       // which row this group handles
    const int t = tid & 15;       // d-chunk (4 columns via float4)
    const int row = row0 + g;
    if (row >= n) return;

    const int len = slen[g];
    // W[row, i, d]: float4 view index = row*1024 + i*16 + t
    const float4* Wr = reinterpret_cast<const float4*>(W) + (size_t)row * 1024 + t;
    const float* xr = sx[g];

    float4 acc = make_float4(0.f, 0.f, 0.f, 0.f);

    int i = 0;
    // Unrolled x4: 4 independent float4 loads in flight per thread
    for (; i + 4 <= len; i += 4) {
        float4 w0 = Wr[(i + 0) * 16];
        float4 w1 = Wr[(i + 1) * 16];
        float4 w2 = Wr[(i + 2) * 16];
        float4 w3 = Wr[(i + 3) * 16];
        float x0 = xr[i + 0], x1 = xr[i + 1], x2 = xr[i + 2], x3 = xr[i + 3];
        acc.x += x0 * w0.x + x1 * w1.x + x2 * w2.x + x3 * w3.x;
        acc.y += x0 * w0.y + x1 * w1.y + x2 * w2.y + x3 * w3.y;
        acc.z += x0 * w0.z + x1 * w1.z + x2 * w2.z + x3 * w3.z;
        acc.w += x0 * w0.w + x1 * w1.w + x2 * w2.w + x3 * w3.w;
    }
    for (; i < len; i++) {
        float4 w = Wr[i * 16];
        float xv = xr[i];
        acc.x += xv * w.x;
        acc.y += xv * w.y;
        acc.z += xv * w.z;
        acc.w += xv * w.w;
    }

    float4 bb = reinterpret_cast<const float4*>(b)[(size_t)row * 16 + t];
    float4 r4;
    r4.x = gelu_tanh(acc.x + bb.x);
    r4.y = gelu_tanh(acc.y + bb.y);
    r4.z = gelu_tanh(acc.z + bb.z);
    r4.w = gelu_tanh(acc.w + bb.w);

    reinterpret_cast<float4*>(out)[(size_t)row * 16 + t] = r4;
}

extern "C" void kernel_launch(void* const* d_in, const int* in_sizes, int n_in,
                              void* d_out, int out_size) {
    const float* seg     = (const float*)d_in[0];   // [N, 64]
    const float* W       = (const float*)d_in[1];   // [N, 64, 64]
    const float* b       = (const float*)d_in[2];   // [N, 64]
    const int*   lengths = (const int*)d_in[3];     // [N]
    float* out = (float*)d_out;                     // [N, 64]

    int n = in_sizes[3];  // number of rows (lengths element count)

    int grid = (n + ROWS_PER_BLOCK - 1) / ROWS_PER_BLOCK;
    fe_kernel<<<grid, THREADS>>>(seg, W, b, lengths, out, n);
}